// round 12
// baseline (speedup 1.0000x reference)
#include <cuda_runtime.h>
#include <cstdint>

typedef unsigned long long ULL;

// ---------------- problem constants -------------------------------------------
#define NVEC   131072          // 16*1024*8 vectors
#define KC     2048            // codebook size
#define DDIM   64              // codebook_dim
#define BM     128             // rows per block
#define BN     64              // codes per chunk
#define NCHUNK (KC / BN)       // 32
#define CODES_ELEMS 8388608
#define GATHER_BLOCKS 8192

// smem layout (bytes): zsT 32KB | csT double buffer 2x16KB | bias 8KB
#define ZS_OFF   0
#define ZS_BYTES (DDIM * BM * 4)            // 32768
#define CS_OFF   ZS_BYTES
#define CS_BYTES (DDIM * BN * 4)            // 16384 per buffer
#define BIAS_OFF (CS_OFF + 2 * CS_BYTES)    // 65536
#define SMEM_TOTAL (BIAS_OFF + KC * 4)      // 73728 -> 3 CTAs/SM = 216KB

// ---------------- device scratch ----------------------------------------------
__device__ __align__(16) float cbT_g[DDIM * KC];    // transposed codebook [d][k]
__device__ __align__(16) float cbias_g[KC];         // 0.5*||c_k||^2
__device__ int   idx_g[NVEC];
__device__ float bsum_g[GATHER_BLOCKS];

// ---------------- helpers -------------------------------------------------------
__device__ __forceinline__ uint32_t smem_u32(const void* p) {
    uint32_t a;
    asm("{ .reg .u64 t; cvta.to.shared.u64 t, %1; cvt.u32.u64 %0, t; }" : "=r"(a) : "l"(p));
    return a;
}
__device__ __forceinline__ ULL fma2(ULL a, ULL b, ULL c) {
    ULL d;
    asm("fma.rn.f32x2 %0, %1, %2, %3;" : "=l"(d) : "l"(a), "l"(b), "l"(c));
    return d;
}
__device__ __forceinline__ ULL dup2(float f) {
    ULL d; unsigned u = __float_as_uint(f);
    asm("mov.b64 %0, {%1, %1};" : "=l"(d) : "r"(u));
    return d;
}
__device__ __forceinline__ void cp16(uint32_t dst, const void* src) {
    asm volatile("cp.async.cg.shared.global [%0], [%1], 16;" :: "r"(dst), "l"(src) : "memory");
}
#define CP_COMMIT() asm volatile("cp.async.commit_group;" ::: "memory")
#define CP_WAIT0()  asm volatile("cp.async.wait_group 0;" ::: "memory")
#define CP_WAIT1()  asm volatile("cp.async.wait_group 1;" ::: "memory")

// ---------------- kernel 0: codebook transpose + bias ---------------------------
__global__ void prep_kernel(const float* __restrict__ cb) {
    int k = blockIdx.x * blockDim.x + threadIdx.x;
    if (k >= KC) return;
    float s = 0.f;
#pragma unroll
    for (int d = 0; d < DDIM; d++) {
        float v = cb[k * DDIM + d];
        s += v * v;
        cbT_g[d * KC + k] = v;
    }
    cbias_g[k] = 0.5f * s;
}

// ---------------- B chunk loader (coalesced 16B copies, conflict-free dst) ------
__device__ __forceinline__ void load_B(int ch, uint32_t cs_buf, int tid) {
    const int c0 = ch * BN;
#pragma unroll
    for (int it = 0; it < 4; it++) {
        int i = it * 256 + tid;          // 0..1023 float4s
        int d = i >> 4, w = i & 15;
        cp16(cs_buf + i * 16, &cbT_g[d * KC + c0 + w * 4]);
    }
}

// ---------------- kernel 1: FFMA2 scores + running argmax -----------------------
// score(n,k) = z_n . c_k - 0.5*||c_k||^2 ; argmax score == argmin distance.
__global__ __launch_bounds__(256, 3)
void argmin_kernel(const float* __restrict__ z, float* __restrict__ out_idx_f,
                   int write_idx) {
    extern __shared__ __align__(16) char smem[];
    float* zsT = (float*)(smem + ZS_OFF);            // [d][row]
    float* bias_sm = (float*)(smem + BIAS_OFF);      // all 2048 biases
    uint32_t sbase = smem_u32(smem);

    const int tid = threadIdx.x;
    const int tx = tid & 15;        // col group: codes tx*4 .. tx*4+3
    const int ty = tid >> 4;        // row group: rows ty*8 .. ty*8+7
    const int m0 = blockIdx.x * BM;

    // ---- load z tile transposed (once per block) ----
    const float4* zg4 = (const float4*)(z + (long)m0 * DDIM);
#pragma unroll
    for (int t = 0; t < 8; t++) {
        int lin = t * 256 + tid;            // 0..2047 float4s
        int row = lin >> 4;
        int d4  = lin & 15;
        float4 v = zg4[lin];
        zsT[(d4 * 4 + 0) * BM + row] = v.x;
        zsT[(d4 * 4 + 1) * BM + row] = v.y;
        zsT[(d4 * 4 + 2) * BM + row] = v.z;
        zsT[(d4 * 4 + 3) * BM + row] = v.w;
    }

    // ---- prologue: async-prefetch bias + chunk 0 (group A), chunk 1 (group B) --
#pragma unroll
    for (int it = 0; it < 2; it++) {
        int i = it * 256 + tid;             // 0..511 float4s (2048 biases)
        cp16(sbase + BIAS_OFF + i * 16, cbias_g + i * 4);
    }
    load_B(0, sbase + CS_OFF, tid);
    CP_COMMIT();
    load_B(1, sbase + CS_OFF + CS_BYTES, tid);
    CP_COMMIT();
    CP_WAIT1();                              // bias + chunk 0 landed
    __syncthreads();                         // zsT + chunk0 + bias visible to all

    float bestv[8];
    int   besti[8];
#pragma unroll
    for (int r = 0; r < 8; r++) { bestv[r] = -3.4e38f; besti[r] = 0; }

#pragma unroll 1
    for (int ch = 0; ch < NCHUNK; ch++) {
        const int c0 = ch * BN;
        const float* csT = (const float*)(smem + CS_OFF + (ch & 1) * CS_BYTES); // [d][64]

        ULL acc[4][4];                      // [row-pair][col], packed f32x2
#pragma unroll
        for (int rp = 0; rp < 4; rp++)
#pragma unroll
            for (int j = 0; j < 4; j++) acc[rp][j] = 0ULL;

#pragma unroll 16
        for (int d = 0; d < DDIM; d++) {
            ulonglong2 a01 = *(const ulonglong2*)&zsT[d * BM + ty * 8];     // rows 0..3
            ulonglong2 a23 = *(const ulonglong2*)&zsT[d * BM + ty * 8 + 4]; // rows 4..7
            float4 bv = *(const float4*)&csT[d * BN + tx * 4];
            ULL b0 = dup2(bv.x), b1 = dup2(bv.y), b2 = dup2(bv.z), b3 = dup2(bv.w);
            acc[0][0] = fma2(a01.x, b0, acc[0][0]);
            acc[0][1] = fma2(a01.x, b1, acc[0][1]);
            acc[0][2] = fma2(a01.x, b2, acc[0][2]);
            acc[0][3] = fma2(a01.x, b3, acc[0][3]);
            acc[1][0] = fma2(a01.y, b0, acc[1][0]);
            acc[1][1] = fma2(a01.y, b1, acc[1][1]);
            acc[1][2] = fma2(a01.y, b2, acc[1][2]);
            acc[1][3] = fma2(a01.y, b3, acc[1][3]);
            acc[2][0] = fma2(a23.x, b0, acc[2][0]);
            acc[2][1] = fma2(a23.x, b1, acc[2][1]);
            acc[2][2] = fma2(a23.x, b2, acc[2][2]);
            acc[2][3] = fma2(a23.x, b3, acc[2][3]);
            acc[3][0] = fma2(a23.y, b0, acc[3][0]);
            acc[3][1] = fma2(a23.y, b1, acc[3][1]);
            acc[3][2] = fma2(a23.y, b2, acc[3][2]);
            acc[3][3] = fma2(a23.y, b3, acc[3][3]);
        }

        // ---- fold chunk into running best (strict >, ascending code => argmin
        //      tie-break to lowest index within a thread); bias from smem ----
#pragma unroll
        for (int j = 0; j < 4; j++) {
            int code = c0 + tx * 4 + j;
            float bias = bias_sm[code];
#pragma unroll
            for (int rp = 0; rp < 4; rp++) {
                ULL v = acc[rp][j];
                float lo = __uint_as_float((unsigned)(v & 0xffffffffULL)) - bias;
                float hi = __uint_as_float((unsigned)(v >> 32)) - bias;
                if (lo > bestv[2 * rp])     { bestv[2 * rp] = lo;     besti[2 * rp] = code; }
                if (hi > bestv[2 * rp + 1]) { bestv[2 * rp + 1] = hi; besti[2 * rp + 1] = code; }
            }
        }

        __syncthreads();                       // all warps done reading this buffer
        if (ch + 2 < NCHUNK) {
            load_B(ch + 2, sbase + CS_OFF + (ch & 1) * CS_BYTES, tid);
            CP_COMMIT();
            CP_WAIT1();                        // chunk ch+1 landed
        } else if (ch + 1 < NCHUNK) {
            CP_WAIT0();
        }
        __syncthreads();
    }

    // ---- reduce across the 16 tx lanes sharing each row ----
#pragma unroll
    for (int r = 0; r < 8; r++) {
        float v = bestv[r];
        int   ix = besti[r];
#pragma unroll
        for (int off = 8; off; off >>= 1) {
            float ov = __shfl_xor_sync(0xffffffffu, v, off);
            int   oi = __shfl_xor_sync(0xffffffffu, ix, off);
            if (ov > v || (ov == v && oi < ix)) { v = ov; ix = oi; }
        }
        if (tx == 0) {
            int row = m0 + ty * 8 + r;
            idx_g[row] = ix;
            if (write_idx) out_idx_f[row] = (float)ix;
        }
    }
}

// ---------------- kernel 2: gather codes + per-block loss partials --------------
__global__ __launch_bounds__(256)
void gather_kernel(const float* __restrict__ z, const float* __restrict__ cb,
                   float* __restrict__ codes_out, int write_codes) {
    const int tid = threadIdx.x;
    const int lin = blockIdx.x * 256 + tid;
    const int n = lin >> 4, d4 = lin & 15;
    const int idx = idx_g[n];
    float4 c  = *(const float4*)&cb[idx * DDIM + d4 * 4];
    float4 zz = *(const float4*)&z[(long)n * DDIM + d4 * 4];
    if (write_codes) *(float4*)&codes_out[(long)n * DDIM + d4 * 4] = c;
    float dx = c.x - zz.x, dy = c.y - zz.y, dz = c.z - zz.z, dw = c.w - zz.w;
    float s = dx * dx + dy * dy + dz * dz + dw * dw;
#pragma unroll
    for (int off = 16; off; off >>= 1) s += __shfl_xor_sync(0xffffffffu, s, off);
    __shared__ float ws[8];
    if ((tid & 31) == 0) ws[tid >> 5] = s;
    __syncthreads();
    if (tid == 0) {
        float t = 0.f;
#pragma unroll
        for (int i = 0; i < 8; i++) t += ws[i];
        bsum_g[blockIdx.x] = t;
    }
}

// ---------------- kernel 3: final deterministic loss reduction ------------------
__global__ __launch_bounds__(256)
void loss_kernel(float* __restrict__ out_loss, int write_loss) {
    __shared__ float sh[256];
    const int tid = threadIdx.x;
    float s = 0.f;
    for (int i = tid; i < GATHER_BLOCKS; i += 256) s += bsum_g[i];
    sh[tid] = s;
    __syncthreads();
    for (int off = 128; off; off >>= 1) {
        if (tid < off) sh[tid] += sh[tid + off];
        __syncthreads();
    }
    if (tid == 0 && write_loss)
        out_loss[0] = sh[0] * (1.0f / 8388608.0f);   // exact 2^-23, == jnp.mean
}

// ---------------- launcher ------------------------------------------------------
extern "C" void kernel_launch(void* const* d_in, const int* in_sizes, int n_in,
                              void* d_out, int out_size) {
    const float* z  = (const float*)d_in[0];
    const float* cb = (const float*)d_in[1];
    if (n_in >= 2 && in_sizes[0] == KC * DDIM) { const float* t = z; z = cb; cb = t; }
    float* out = (float*)d_out;

    const long idx_off  = (long)CODES_ELEMS;
    const long loss_off = (long)CODES_ELEMS + NVEC;
    const int have_codes = out_size >= CODES_ELEMS;
    const int have_idx   = out_size >= CODES_ELEMS + NVEC;
    const int have_loss  = out_size >= CODES_ELEMS + NVEC + 1;

    cudaFuncSetAttribute(argmin_kernel,
                         cudaFuncAttributeMaxDynamicSharedMemorySize, SMEM_TOTAL);

    prep_kernel<<<(KC + 255) / 256, 256>>>(cb);
    argmin_kernel<<<NVEC / BM, 256, SMEM_TOTAL>>>(z, out + idx_off, have_idx);
    gather_kernel<<<GATHER_BLOCKS, 256>>>(z, cb, out, have_codes);
    loss_kernel<<<1, 256>>>(out + loss_off, have_loss);
}

// round 13
// speedup vs baseline: 1.0361x; 1.0361x over previous
#include <cuda_runtime.h>
#include <cstdint>

typedef unsigned long long ULL;

// ---------------- problem constants -------------------------------------------
#define NVEC   131072          // 16*1024*8 vectors
#define KC     2048            // codebook size
#define DDIM   64              // codebook_dim
#define BM     128             // rows per block
#define BN     64              // codes per chunk
#define NCHUNK (KC / BN)       // 32
#define CODES_ELEMS 8388608
#define GATHER_BLOCKS 8192

// smem layout (bytes): zsT 32KB | csT triple buffer 3x16KB | bias 8KB
#define ZS_OFF   0
#define ZS_BYTES (DDIM * BM * 4)            // 32768
#define CS_OFF   ZS_BYTES
#define CS_BYTES (DDIM * BN * 4)            // 16384 per buffer
#define BIAS_OFF (CS_OFF + 3 * CS_BYTES)    // 81920
#define SMEM_TOTAL (BIAS_OFF + KC * 4)      // 90112 -> 2 CTAs/SM = 180KB

// ---------------- device scratch ----------------------------------------------
__device__ __align__(16) float cbT_g[DDIM * KC];    // transposed codebook [d][k]
__device__ __align__(16) float cbias_g[KC];         // 0.5*||c_k||^2
__device__ int   idx_g[NVEC];
__device__ float bsum_g[GATHER_BLOCKS];
__device__ unsigned int done_ctr;

// ---------------- helpers -------------------------------------------------------
__device__ __forceinline__ uint32_t smem_u32(const void* p) {
    uint32_t a;
    asm("{ .reg .u64 t; cvta.to.shared.u64 t, %1; cvt.u32.u64 %0, t; }" : "=r"(a) : "l"(p));
    return a;
}
__device__ __forceinline__ ULL fma2(ULL a, ULL b, ULL c) {
    ULL d;
    asm("fma.rn.f32x2 %0, %1, %2, %3;" : "=l"(d) : "l"(a), "l"(b), "l"(c));
    return d;
}
__device__ __forceinline__ ULL dup2(float f) {
    ULL d; unsigned u = __float_as_uint(f);
    asm("mov.b64 %0, {%1, %1};" : "=l"(d) : "r"(u));
    return d;
}
__device__ __forceinline__ void cp16(uint32_t dst, const void* src) {
    asm volatile("cp.async.cg.shared.global [%0], [%1], 16;" :: "r"(dst), "l"(src) : "memory");
}
#define CP_COMMIT() asm volatile("cp.async.commit_group;" ::: "memory")
#define CP_WAIT0()  asm volatile("cp.async.wait_group 0;" ::: "memory")
#define CP_WAIT1()  asm volatile("cp.async.wait_group 1;" ::: "memory")

// ---------------- kernel 0: codebook transpose + bias + counter reset -----------
__global__ void prep_kernel(const float* __restrict__ cb) {
    int k = blockIdx.x * blockDim.x + threadIdx.x;
    if (k == 0) done_ctr = 0u;
    if (k >= KC) return;
    float s = 0.f;
#pragma unroll
    for (int d = 0; d < DDIM; d++) {
        float v = cb[k * DDIM + d];
        s += v * v;
        cbT_g[d * KC + k] = v;
    }
    cbias_g[k] = 0.5f * s;
}

// ---------------- B chunk loader (coalesced 16B copies, conflict-free dst) ------
__device__ __forceinline__ void load_B(int ch, uint32_t cs_buf, int tid) {
    const int c0 = ch * BN;
#pragma unroll
    for (int it = 0; it < 4; it++) {
        int i = it * 256 + tid;          // 0..1023 float4s
        int d = i >> 4, w = i & 15;
        cp16(cs_buf + i * 16, &cbT_g[d * KC + c0 + w * 4]);
    }
}

// ---------------- kernel 1: FFMA2 scores + running argmax -----------------------
// score(n,k) = z_n . c_k - 0.5*||c_k||^2 ; argmax score == argmin distance.
__global__ __launch_bounds__(256, 2)
void argmin_kernel(const float* __restrict__ z) {
    extern __shared__ __align__(16) char smem[];
    float* zsT = (float*)(smem + ZS_OFF);            // [d][row]
    float* bias_sm = (float*)(smem + BIAS_OFF);      // all 2048 biases
    uint32_t sbase = smem_u32(smem);

    const int tid = threadIdx.x;
    const int tx = tid & 15;        // col group: codes tx*4 .. tx*4+3
    const int ty = tid >> 4;        // row group: rows ty*8 .. ty*8+7
    const int m0 = blockIdx.x * BM;

    // ---- prologue: group0 = bias + chunk0, group1 = chunk1 ----
#pragma unroll
    for (int it = 0; it < 2; it++) {
        int i = it * 256 + tid;             // 0..511 float4s (2048 biases)
        cp16(sbase + BIAS_OFF + i * 16, cbias_g + i * 4);
    }
    load_B(0, sbase + CS_OFF, tid);
    CP_COMMIT();
    load_B(1, sbase + CS_OFF + CS_BYTES, tid);
    CP_COMMIT();

    // ---- load z tile transposed (plain stores; published by first barrier) ----
    const float4* zg4 = (const float4*)(z + (long)m0 * DDIM);
#pragma unroll
    for (int t = 0; t < 8; t++) {
        int lin = t * 256 + tid;            // 0..2047 float4s
        int row = lin >> 4;
        int d4  = lin & 15;
        float4 v = zg4[lin];
        zsT[(d4 * 4 + 0) * BM + row] = v.x;
        zsT[(d4 * 4 + 1) * BM + row] = v.y;
        zsT[(d4 * 4 + 2) * BM + row] = v.z;
        zsT[(d4 * 4 + 3) * BM + row] = v.w;
    }

    float bestv[8];
    int   besti[8];
#pragma unroll
    for (int r = 0; r < 8; r++) { bestv[r] = -3.4e38f; besti[r] = 0; }

    // ---- main loop: triple-buffered ring, ONE barrier per chunk ----
    // Invariant at top of iter ch: outstanding groups = {ch, ch+1} (last iter: {ch}).
    // WAIT -> chunk ch landed; BARRIER -> all warps done with iter ch-1 AND
    // chunk ch (+ zsT/bias on iter 0) visible to all. The load issued at the end
    // of iter ch targets buf[(ch+2)%3] == buf[(ch-1)%3], last read in iter ch-1
    // (all warps past the barrier), so no race.
#pragma unroll 1
    for (int ch = 0; ch < NCHUNK; ch++) {
        if (ch == NCHUNK - 1) CP_WAIT0(); else CP_WAIT1();
        __syncthreads();

        const int c0 = ch * BN;
        const float* csT = (const float*)(smem + CS_OFF + (ch % 3) * CS_BYTES); // [d][64]

        ULL acc[4][4];                      // [row-pair][col], packed f32x2
#pragma unroll
        for (int rp = 0; rp < 4; rp++)
#pragma unroll
            for (int j = 0; j < 4; j++) acc[rp][j] = 0ULL;

#pragma unroll 16
        for (int d = 0; d < DDIM; d++) {
            ulonglong2 a01 = *(const ulonglong2*)&zsT[d * BM + ty * 8];     // rows 0..3
            ulonglong2 a23 = *(const ulonglong2*)&zsT[d * BM + ty * 8 + 4]; // rows 4..7
            float4 bv = *(const float4*)&csT[d * BN + tx * 4];
            ULL b0 = dup2(bv.x), b1 = dup2(bv.y), b2 = dup2(bv.z), b3 = dup2(bv.w);
            acc[0][0] = fma2(a01.x, b0, acc[0][0]);
            acc[0][1] = fma2(a01.x, b1, acc[0][1]);
            acc[0][2] = fma2(a01.x, b2, acc[0][2]);
            acc[0][3] = fma2(a01.x, b3, acc[0][3]);
            acc[1][0] = fma2(a01.y, b0, acc[1][0]);
            acc[1][1] = fma2(a01.y, b1, acc[1][1]);
            acc[1][2] = fma2(a01.y, b2, acc[1][2]);
            acc[1][3] = fma2(a01.y, b3, acc[1][3]);
            acc[2][0] = fma2(a23.x, b0, acc[2][0]);
            acc[2][1] = fma2(a23.x, b1, acc[2][1]);
            acc[2][2] = fma2(a23.x, b2, acc[2][2]);
            acc[2][3] = fma2(a23.x, b3, acc[2][3]);
            acc[3][0] = fma2(a23.y, b0, acc[3][0]);
            acc[3][1] = fma2(a23.y, b1, acc[3][1]);
            acc[3][2] = fma2(a23.y, b2, acc[3][2]);
            acc[3][3] = fma2(a23.y, b3, acc[3][3]);
        }

        // ---- fold chunk into running best (strict >, ascending code => argmin
        //      tie-break to lowest index within a thread); bias from smem ----
#pragma unroll
        for (int j = 0; j < 4; j++) {
            int code = c0 + tx * 4 + j;
            float bias = bias_sm[code];
#pragma unroll
            for (int rp = 0; rp < 4; rp++) {
                ULL v = acc[rp][j];
                float lo = __uint_as_float((unsigned)(v & 0xffffffffULL)) - bias;
                float hi = __uint_as_float((unsigned)(v >> 32)) - bias;
                if (lo > bestv[2 * rp])     { bestv[2 * rp] = lo;     besti[2 * rp] = code; }
                if (hi > bestv[2 * rp + 1]) { bestv[2 * rp + 1] = hi; besti[2 * rp + 1] = code; }
            }
        }

        if (ch + 2 < NCHUNK) {
            load_B(ch + 2, sbase + CS_OFF + ((ch + 2) % 3) * CS_BYTES, tid);
            CP_COMMIT();
        }
    }

    // ---- reduce across the 16 tx lanes sharing each row ----
#pragma unroll
    for (int r = 0; r < 8; r++) {
        float v = bestv[r];
        int   ix = besti[r];
#pragma unroll
        for (int off = 8; off; off >>= 1) {
            float ov = __shfl_xor_sync(0xffffffffu, v, off);
            int   oi = __shfl_xor_sync(0xffffffffu, ix, off);
            if (ov > v || (ov == v && oi < ix)) { v = ov; ix = oi; }
        }
        if (tx == 0) idx_g[m0 + ty * 8 + r] = ix;
    }
}

// ---------------- kernel 2: gather codes + idx + fused deterministic loss -------
__global__ __launch_bounds__(256)
void gather_kernel(const float* __restrict__ z, const float* __restrict__ cb,
                   float* __restrict__ codes_out, float* __restrict__ out_idx_f,
                   float* __restrict__ out_loss,
                   int write_codes, int write_idx, int write_loss) {
    const int tid = threadIdx.x;
    const int lin = blockIdx.x * 256 + tid;
    const int n = lin >> 4, d4 = lin & 15;
    const int idx = idx_g[n];
    float4 c  = *(const float4*)&cb[idx * DDIM + d4 * 4];
    float4 zz = *(const float4*)&z[(long)n * DDIM + d4 * 4];
    if (write_codes) *(float4*)&codes_out[(long)n * DDIM + d4 * 4] = c;
    if (d4 == 0 && write_idx) out_idx_f[n] = (float)idx;
    float dx = c.x - zz.x, dy = c.y - zz.y, dz = c.z - zz.z, dw = c.w - zz.w;
    float s = dx * dx + dy * dy + dz * dz + dw * dw;
#pragma unroll
    for (int off = 16; off; off >>= 1) s += __shfl_xor_sync(0xffffffffu, s, off);
    __shared__ float ws[8];
    if ((tid & 31) == 0) ws[tid >> 5] = s;
    __syncthreads();
    if (tid == 0) {
        float t = 0.f;
#pragma unroll
        for (int i = 0; i < 8; i++) t += ws[i];
        bsum_g[blockIdx.x] = t;
    }

    // ---- last-block final reduction (deterministic: fixed-order sum) ----
    __shared__ unsigned int amLast;
    __threadfence();
    if (tid == 0) {
        unsigned int old = atomicAdd(&done_ctr, 1u);
        amLast = (old == GATHER_BLOCKS - 1) ? 1u : 0u;
    }
    __syncthreads();
    if (amLast) {
        __shared__ float sh[256];
        float acc = 0.f;
        for (int i = tid; i < GATHER_BLOCKS; i += 256) acc += bsum_g[i];
        sh[tid] = acc;
        __syncthreads();
        for (int off = 128; off; off >>= 1) {
            if (tid < off) sh[tid] += sh[tid + off];
            __syncthreads();
        }
        if (tid == 0 && write_loss)
            out_loss[0] = sh[0] * (1.0f / 8388608.0f);   // exact 2^-23, == jnp.mean
    }
}

// ---------------- launcher ------------------------------------------------------
extern "C" void kernel_launch(void* const* d_in, const int* in_sizes, int n_in,
                              void* d_out, int out_size) {
    const float* z  = (const float*)d_in[0];
    const float* cb = (const float*)d_in[1];
    if (n_in >= 2 && in_sizes[0] == KC * DDIM) { const float* t = z; z = cb; cb = t; }
    float* out = (float*)d_out;

    const long idx_off  = (long)CODES_ELEMS;
    const long loss_off = (long)CODES_ELEMS + NVEC;
    const int have_codes = out_size >= CODES_ELEMS;
    const int have_idx   = out_size >= CODES_ELEMS + NVEC;
    const int have_loss  = out_size >= CODES_ELEMS + NVEC + 1;

    cudaFuncSetAttribute(argmin_kernel,
                         cudaFuncAttributeMaxDynamicSharedMemorySize, SMEM_TOTAL);

    prep_kernel<<<(KC + 255) / 256, 256>>>(cb);
    argmin_kernel<<<NVEC / BM, 256, SMEM_TOTAL>>>(z);
    gather_kernel<<<GATHER_BLOCKS, 256>>>(z, cb, out, out + idx_off, out + loss_off,
                                          have_codes, have_idx, have_loss);
}

// round 14
// speedup vs baseline: 1.0684x; 1.0312x over previous
#include <cuda_runtime.h>
#include <cstdint>

typedef unsigned long long ULL;

// ---------------- problem constants -------------------------------------------
#define NVEC   131072          // 16*1024*8 vectors
#define KC     2048            // codebook size
#define DDIM   64              // codebook_dim
#define BM     128             // rows per block
#define BN     64              // codes per chunk
#define NCHUNK (KC / BN)       // 32
#define CODES_ELEMS 8388608
#define GATHER_BLOCKS 8192

// smem layout (bytes): zsT 32KB | csT double buffer 2x16KB | bias 8KB
#define ZS_OFF   0
#define ZS_BYTES (DDIM * BM * 4)            // 32768
#define CS_OFF   ZS_BYTES
#define CS_BYTES (DDIM * BN * 4)            // 16384 per buffer
#define BIAS_OFF (CS_OFF + 2 * CS_BYTES)    // 65536
#define SMEM_TOTAL (BIAS_OFF + KC * 4)      // 73728

// ---------------- device scratch ----------------------------------------------
__device__ __align__(16) float cbT_g[DDIM * KC];    // transposed codebook [d][k]
__device__ __align__(16) float cbias_g[KC];         // 0.5*||c_k||^2
__device__ int   idx_g[NVEC];
__device__ float bsum_g[GATHER_BLOCKS];

// ---------------- helpers -------------------------------------------------------
__device__ __forceinline__ uint32_t smem_u32(const void* p) {
    uint32_t a;
    asm("{ .reg .u64 t; cvta.to.shared.u64 t, %1; cvt.u32.u64 %0, t; }" : "=r"(a) : "l"(p));
    return a;
}
__device__ __forceinline__ ULL fma2(ULL a, ULL b, ULL c) {
    ULL d;
    asm("fma.rn.f32x2 %0, %1, %2, %3;" : "=l"(d) : "l"(a), "l"(b), "l"(c));
    return d;
}
__device__ __forceinline__ ULL dup2(float f) {
    ULL d; unsigned u = __float_as_uint(f);
    asm("mov.b64 %0, {%1, %1};" : "=l"(d) : "r"(u));
    return d;
}
__device__ __forceinline__ void cp16(uint32_t dst, const void* src) {
    asm volatile("cp.async.cg.shared.global [%0], [%1], 16;" :: "r"(dst), "l"(src) : "memory");
}
#define CP_COMMIT() asm volatile("cp.async.commit_group;" ::: "memory")
#define CP_WAIT0()  asm volatile("cp.async.wait_group 0;" ::: "memory")
#define CP_WAIT1()  asm volatile("cp.async.wait_group 1;" ::: "memory")

// ---------------- kernel 0: tiled codebook transpose + bias ---------------------
// 32 blocks x 256 threads; each block transposes a 64(k) x 64(d) tile via smem.
__global__ __launch_bounds__(256) void prep_kernel(const float* __restrict__ cb) {
    __shared__ float tile[64][65];                   // padded: conflict-light
    const int tid = threadIdx.x;
    const int k0 = blockIdx.x * 64;

    // coalesced float4 reads: row r = k-local, c4 = d-group
#pragma unroll
    for (int it = 0; it < 4; it++) {
        int i = it * 256 + tid;                      // 0..1023 float4s
        int r = i >> 4, c4 = i & 15;
        float4 v = *(const float4*)&cb[(long)(k0 + r) * DDIM + c4 * 4];
        tile[r][c4 * 4 + 0] = v.x;
        tile[r][c4 * 4 + 1] = v.y;
        tile[r][c4 * 4 + 2] = v.z;
        tile[r][c4 * 4 + 3] = v.w;
    }
    __syncthreads();

    // bias: one thread per k-row, ascending-d sum (matches original order)
    if (tid < 64) {
        float s = 0.f;
#pragma unroll
        for (int d = 0; d < DDIM; d++) {
            float v = tile[tid][d];
            s += v * v;
        }
        cbias_g[k0 + tid] = 0.5f * s;
    }

    // coalesced float4 writes of the transpose: cbT[d][k0 + w*4 .. +3]
#pragma unroll
    for (int it = 0; it < 4; it++) {
        int i = it * 256 + tid;                      // 0..1023 float4s
        int d = i >> 4, w = i & 15;
        float4 o;
        o.x = tile[w * 4 + 0][d];
        o.y = tile[w * 4 + 1][d];
        o.z = tile[w * 4 + 2][d];
        o.w = tile[w * 4 + 3][d];
        *(float4*)&cbT_g[(long)d * KC + k0 + w * 4] = o;
    }
}

// ---------------- B chunk loader (coalesced 16B copies, conflict-free dst) ------
__device__ __forceinline__ void load_B(int ch, uint32_t cs_buf, int tid) {
    const int c0 = ch * BN;
#pragma unroll
    for (int it = 0; it < 4; it++) {
        int i = it * 256 + tid;          // 0..1023 float4s
        int d = i >> 4, w = i & 15;
        cp16(cs_buf + i * 16, &cbT_g[d * KC + c0 + w * 4]);
    }
}

// ---------------- kernel 1: FFMA2 scores + running argmax -----------------------
// score(n,k) = z_n . c_k - 0.5*||c_k||^2 ; argmax score == argmin distance.
__global__ __launch_bounds__(256, 2)
void argmin_kernel(const float* __restrict__ z, float* __restrict__ out_idx_f,
                   int write_idx) {
    extern __shared__ __align__(16) char smem[];
    float* zsT = (float*)(smem + ZS_OFF);            // [d][row]
    float* bias_sm = (float*)(smem + BIAS_OFF);      // all 2048 biases
    uint32_t sbase = smem_u32(smem);

    const int tid = threadIdx.x;
    const int tx = tid & 15;        // col group: codes tx*4 .. tx*4+3
    const int ty = tid >> 4;        // row group: rows ty*8 .. ty*8+7
    const int m0 = blockIdx.x * BM;

    // ---- load z tile transposed (once per block) ----
    const float4* zg4 = (const float4*)(z + (long)m0 * DDIM);
#pragma unroll
    for (int t = 0; t < 8; t++) {
        int lin = t * 256 + tid;            // 0..2047 float4s
        int row = lin >> 4;
        int d4  = lin & 15;
        float4 v = zg4[lin];
        zsT[(d4 * 4 + 0) * BM + row] = v.x;
        zsT[(d4 * 4 + 1) * BM + row] = v.y;
        zsT[(d4 * 4 + 2) * BM + row] = v.z;
        zsT[(d4 * 4 + 3) * BM + row] = v.w;
    }

    // ---- prologue: async-prefetch bias + chunk 0 (group A), chunk 1 (group B) --
#pragma unroll
    for (int it = 0; it < 2; it++) {
        int i = it * 256 + tid;             // 0..511 float4s (2048 biases)
        cp16(sbase + BIAS_OFF + i * 16, cbias_g + i * 4);
    }
    load_B(0, sbase + CS_OFF, tid);
    CP_COMMIT();
    load_B(1, sbase + CS_OFF + CS_BYTES, tid);
    CP_COMMIT();
    CP_WAIT1();                              // bias + chunk 0 landed
    __syncthreads();                         // zsT + chunk0 + bias visible to all

    float bestv[8];
    int   besti[8];
#pragma unroll
    for (int r = 0; r < 8; r++) { bestv[r] = -3.4e38f; besti[r] = 0; }

#pragma unroll 1
    for (int ch = 0; ch < NCHUNK; ch++) {
        const int c0 = ch * BN;
        const float* csT = (const float*)(smem + CS_OFF + (ch & 1) * CS_BYTES); // [d][64]

        ULL acc[4][4];                      // [row-pair][col], packed f32x2
#pragma unroll
        for (int rp = 0; rp < 4; rp++)
#pragma unroll
            for (int j = 0; j < 4; j++) acc[rp][j] = 0ULL;

#pragma unroll 16
        for (int d = 0; d < DDIM; d++) {
            ulonglong2 a01 = *(const ulonglong2*)&zsT[d * BM + ty * 8];     // rows 0..3
            ulonglong2 a23 = *(const ulonglong2*)&zsT[d * BM + ty * 8 + 4]; // rows 4..7
            float4 bv = *(const float4*)&csT[d * BN + tx * 4];
            ULL b0 = dup2(bv.x), b1 = dup2(bv.y), b2 = dup2(bv.z), b3 = dup2(bv.w);
            acc[0][0] = fma2(a01.x, b0, acc[0][0]);
            acc[0][1] = fma2(a01.x, b1, acc[0][1]);
            acc[0][2] = fma2(a01.x, b2, acc[0][2]);
            acc[0][3] = fma2(a01.x, b3, acc[0][3]);
            acc[1][0] = fma2(a01.y, b0, acc[1][0]);
            acc[1][1] = fma2(a01.y, b1, acc[1][1]);
            acc[1][2] = fma2(a01.y, b2, acc[1][2]);
            acc[1][3] = fma2(a01.y, b3, acc[1][3]);
            acc[2][0] = fma2(a23.x, b0, acc[2][0]);
            acc[2][1] = fma2(a23.x, b1, acc[2][1]);
            acc[2][2] = fma2(a23.x, b2, acc[2][2]);
            acc[2][3] = fma2(a23.x, b3, acc[2][3]);
            acc[3][0] = fma2(a23.y, b0, acc[3][0]);
            acc[3][1] = fma2(a23.y, b1, acc[3][1]);
            acc[3][2] = fma2(a23.y, b2, acc[3][2]);
            acc[3][3] = fma2(a23.y, b3, acc[3][3]);
        }

        // ---- fold chunk into running best (strict >, ascending code => argmin
        //      tie-break to lowest index within a thread); bias from smem ----
#pragma unroll
        for (int j = 0; j < 4; j++) {
            int code = c0 + tx * 4 + j;
            float bias = bias_sm[code];
#pragma unroll
            for (int rp = 0; rp < 4; rp++) {
                ULL v = acc[rp][j];
                float lo = __uint_as_float((unsigned)(v & 0xffffffffULL)) - bias;
                float hi = __uint_as_float((unsigned)(v >> 32)) - bias;
                if (lo > bestv[2 * rp])     { bestv[2 * rp] = lo;     besti[2 * rp] = code; }
                if (hi > bestv[2 * rp + 1]) { bestv[2 * rp + 1] = hi; besti[2 * rp + 1] = code; }
            }
        }

        __syncthreads();                       // all warps done reading this buffer
        if (ch + 2 < NCHUNK) {
            load_B(ch + 2, sbase + CS_OFF + (ch & 1) * CS_BYTES, tid);
            CP_COMMIT();
            CP_WAIT1();                        // chunk ch+1 landed
        } else if (ch + 1 < NCHUNK) {
            CP_WAIT0();
        }
        __syncthreads();
    }

    // ---- reduce across the 16 tx lanes sharing each row ----
#pragma unroll
    for (int r = 0; r < 8; r++) {
        float v = bestv[r];
        int   ix = besti[r];
#pragma unroll
        for (int off = 8; off; off >>= 1) {
            float ov = __shfl_xor_sync(0xffffffffu, v, off);
            int   oi = __shfl_xor_sync(0xffffffffu, ix, off);
            if (ov > v || (ov == v && oi < ix)) { v = ov; ix = oi; }
        }
        if (tx == 0) {
            int row = m0 + ty * 8 + r;
            idx_g[row] = ix;
            if (write_idx) out_idx_f[row] = (float)ix;
        }
    }
}

// ---------------- kernel 2: gather codes + per-block loss partials --------------
__global__ __launch_bounds__(256)
void gather_kernel(const float* __restrict__ z, const float* __restrict__ cb,
                   float* __restrict__ codes_out, int write_codes) {
    const int tid = threadIdx.x;
    const int lin = blockIdx.x * 256 + tid;
    const int n = lin >> 4, d4 = lin & 15;
    const int idx = idx_g[n];
    float4 c  = *(const float4*)&cb[idx * DDIM + d4 * 4];
    float4 zz = *(const float4*)&z[(long)n * DDIM + d4 * 4];
    if (write_codes) *(float4*)&codes_out[(long)n * DDIM + d4 * 4] = c;
    float dx = c.x - zz.x, dy = c.y - zz.y, dz = c.z - zz.z, dw = c.w - zz.w;
    float s = dx * dx + dy * dy + dz * dz + dw * dw;
#pragma unroll
    for (int off = 16; off; off >>= 1) s += __shfl_xor_sync(0xffffffffu, s, off);
    __shared__ float ws[8];
    if ((tid & 31) == 0) ws[tid >> 5] = s;
    __syncthreads();
    if (tid == 0) {
        float t = 0.f;
#pragma unroll
        for (int i = 0; i < 8; i++) t += ws[i];
        bsum_g[blockIdx.x] = t;
    }
}

// ---------------- kernel 3: final deterministic loss reduction ------------------
__global__ __launch_bounds__(256)
void loss_kernel(float* __restrict__ out_loss, int write_loss) {
    __shared__ float sh[256];
    const int tid = threadIdx.x;
    float s = 0.f;
    for (int i = tid; i < GATHER_BLOCKS; i += 256) s += bsum_g[i];
    sh[tid] = s;
    __syncthreads();
    for (int off = 128; off; off >>= 1) {
        if (tid < off) sh[tid] += sh[tid + off];
        __syncthreads();
    }
    if (tid == 0 && write_loss)
        out_loss[0] = sh[0] * (1.0f / 8388608.0f);   // exact 2^-23, == jnp.mean
}

// ---------------- launcher ------------------------------------------------------
extern "C" void kernel_launch(void* const* d_in, const int* in_sizes, int n_in,
                              void* d_out, int out_size) {
    const float* z  = (const float*)d_in[0];
    const float* cb = (const float*)d_in[1];
    if (n_in >= 2 && in_sizes[0] == KC * DDIM) { const float* t = z; z = cb; cb = t; }
    float* out = (float*)d_out;

    const long idx_off  = (long)CODES_ELEMS;
    const long loss_off = (long)CODES_ELEMS + NVEC;
    const int have_codes = out_size >= CODES_ELEMS;
    const int have_idx   = out_size >= CODES_ELEMS + NVEC;
    const int have_loss  = out_size >= CODES_ELEMS + NVEC + 1;

    cudaFuncSetAttribute(argmin_kernel,
                         cudaFuncAttributeMaxDynamicSharedMemorySize, SMEM_TOTAL);

    prep_kernel<<<KC / 64, 256>>>(cb);
    argmin_kernel<<<NVEC / BM, 256, SMEM_TOTAL>>>(z, out + idx_off, have_idx);
    gather_kernel<<<GATHER_BLOCKS, 256>>>(z, cb, out, have_codes);
    loss_kernel<<<1, 256>>>(out + loss_off, have_loss);
}